// round 1
// baseline (speedup 1.0000x reference)
#include <cuda_runtime.h>
#include <cuda_bf16.h>
#include <math.h>

#define V 50257
#define D 128
#define B 1024
#define C 10
#define TWO_D 256

#define BT 64          // batch tile (vocab GEMM)
#define VT 256         // vocab tile
#define KT 32          // k chunk
#define NCHUNK ((V + VT - 1) / VT)   // 197

// ---------------- scratch (no cudaMalloc allowed) ----------------
__device__ float g_z[B * D];
__device__ float g_kl[B];
__device__ float g_pmax[B * NCHUNK];
__device__ float g_psum[B * NCHUNK];
__device__ float g_rowval[B];

__device__ __forceinline__ float softplus_f(float x) {
    // stable: max(x,0) + log1p(exp(-|x|))
    return fmaxf(x, 0.f) + log1pf(expf(-fabsf(x)));
}

// ---------------- kernel 1: encoder + heads + KL + z ----------------
__global__ void __launch_bounds__(256) encoder_kernel(
    const int* __restrict__ center_id, const int* __restrict__ context_ids,
    const float* __restrict__ epsilon, const float* __restrict__ emb,
    const float* __restrict__ prior_means, const float* __restrict__ prior_vars,
    const float* __restrict__ W_enc, const float* __restrict__ b_enc,
    const float* __restrict__ W_mean, const float* __restrict__ b_mean,
    const float* __restrict__ W_var, const float* __restrict__ b_var)
{
    __shared__ float ce_s[D];
    __shared__ float cx_s[C][D];
    __shared__ float h_s[TWO_D];
    __shared__ float mean_s[D];
    __shared__ float var_s[D];
    __shared__ int   ctx_s[C];
    __shared__ float red_s[8];

    const int b = blockIdx.x;
    const int tid = threadIdx.x;
    const int cid = center_id[b];

    if (tid < D) ce_s[tid] = emb[cid * D + tid];
    if (tid < C) ctx_s[tid] = context_ids[b * C + tid];
    __syncthreads();
    for (int e = tid; e < C * D; e += 256) {
        int c = e >> 7, d = e & 127;
        cx_s[c][d] = emb[ctx_s[c] * D + d];
    }
    __syncthreads();

    // h[j] = sum_c relu( ce . Wenc[:128, j] + cx_c . Wenc[128:, j] + b_enc[j] )
    const int j = tid;
    float cepart = 0.f;
    #pragma unroll 4
    for (int k = 0; k < D; k++)
        cepart = fmaf(ce_s[k], W_enc[k * TWO_D + j], cepart);

    float acc[C];
    #pragma unroll
    for (int c = 0; c < C; c++) acc[c] = 0.f;
    #pragma unroll 2
    for (int k = 0; k < D; k++) {
        float w = W_enc[(D + k) * TWO_D + j];
        #pragma unroll
        for (int c = 0; c < C; c++)
            acc[c] = fmaf(cx_s[c][k], w, acc[c]);
    }
    float base = cepart + b_enc[j];
    float hj = 0.f;
    #pragma unroll
    for (int c = 0; c < C; c++) hj += fmaxf(acc[c] + base, 0.f);
    h_s[j] = hj;
    __syncthreads();

    // mean (threads 0..127), var (threads 128..255)
    if (tid < D) {
        float m = b_mean[tid];
        #pragma unroll 4
        for (int k = 0; k < TWO_D; k++)
            m = fmaf(h_s[k], W_mean[k * D + tid], m);
        mean_s[tid] = m;
    } else {
        int d = tid - D;
        float vr = b_var[d];
        #pragma unroll 4
        for (int k = 0; k < TWO_D; k++)
            vr = fmaf(h_s[k], W_var[k * D + d], vr);
        var_s[d] = softplus_f(vr);
    }
    __syncthreads();

    float term = 0.f;
    if (tid < D) {
        int d = tid;
        float m = mean_s[d];
        float v = var_s[d];
        g_z[b * D + d] = m + expf(0.5f * v) * epsilon[d];
        float pm = prior_means[cid * D + d];
        float pv = softplus_f(prior_vars[cid * D + d]);
        float diff = pm - m;
        term = v / pv + diff * diff / pv - 1.f + logf(pv) - logf(v);
    }
    // block reduce (256 threads, term==0 for upper half)
    #pragma unroll
    for (int o = 16; o; o >>= 1) term += __shfl_xor_sync(0xffffffffu, term, o);
    if ((tid & 31) == 0) red_s[tid >> 5] = term;
    __syncthreads();
    if (tid == 0) {
        float s = 0.f;
        #pragma unroll
        for (int w = 0; w < 8; w++) s += red_s[w];
        g_kl[b] = 0.5f * s;
    }
}

// ---------------- kernel 2: vocab GEMM + fused softmax partials ----------------
__global__ void __launch_bounds__(256, 2) vocab_kernel(
    const float* __restrict__ Wv, const float* __restrict__ bvoc)
{
    __shared__ float Ws[KT][VT];        // 32 KB
    __shared__ float zs[BT][KT + 1];    // padded: conflict-free

    const int tid = threadIdx.x;
    const int tx = tid & 31;
    const int ty = tid >> 5;
    const int b0 = blockIdx.y * BT;
    const int v0 = blockIdx.x * VT;

    float acc[8][8];
    #pragma unroll
    for (int i = 0; i < 8; i++)
        #pragma unroll
        for (int j = 0; j < 8; j++) acc[i][j] = 0.f;

    for (int k0 = 0; k0 < D; k0 += KT) {
        #pragma unroll
        for (int i = 0; i < KT; i++) {
            int v = v0 + tid;
            Ws[i][tid] = (v < V) ? Wv[(k0 + i) * V + v] : 0.f;
        }
        #pragma unroll
        for (int i = 0; i < 8; i++) {
            int e = tid + 256 * i;
            int r = e >> 5, kk = e & 31;
            zs[r][kk] = g_z[(b0 + r) * D + k0 + kk];
        }
        __syncthreads();
        #pragma unroll
        for (int kk = 0; kk < KT; kk++) {
            float a[8], w[8];
            #pragma unroll
            for (int i = 0; i < 8; i++) a[i] = zs[ty * 8 + i][kk];
            #pragma unroll
            for (int j = 0; j < 8; j++) w[j] = Ws[kk][tx * 8 + j];
            #pragma unroll
            for (int i = 0; i < 8; i++)
                #pragma unroll
                for (int j = 0; j < 8; j++)
                    acc[i][j] = fmaf(a[i], w[j], acc[i][j]);
        }
        __syncthreads();
    }

    // epilogue: add bias, per-row max & sumexp over this 256-col chunk
    float bv[8];
    bool ok[8];
    #pragma unroll
    for (int j = 0; j < 8; j++) {
        int v = v0 + tx * 8 + j;
        ok[j] = (v < V);
        bv[j] = ok[j] ? bvoc[v] : 0.f;
    }
    const int chunk = blockIdx.x;
    #pragma unroll
    for (int i = 0; i < 8; i++) {
        float m = -INFINITY;
        #pragma unroll
        for (int j = 0; j < 8; j++) {
            float l = acc[i][j] + bv[j];
            acc[i][j] = l;
            if (ok[j] && l > m) m = l;
        }
        #pragma unroll
        for (int o = 16; o; o >>= 1) m = fmaxf(m, __shfl_xor_sync(0xffffffffu, m, o));
        float s = 0.f;
        #pragma unroll
        for (int j = 0; j < 8; j++)
            if (ok[j]) s += __expf(acc[i][j] - m);
        #pragma unroll
        for (int o = 16; o; o >>= 1) s += __shfl_xor_sync(0xffffffffu, s, o);
        if (tx == 0) {
            int row = b0 + ty * 8 + i;
            g_pmax[row * NCHUNK + chunk] = m;
            g_psum[row * NCHUNK + chunk] = s;
        }
    }
}

// ---------------- kernel 3: per-row logsumexp combine + context gather ----------------
__global__ void __launch_bounds__(128) finalize_rows(
    const float* __restrict__ Wv, const float* __restrict__ bvoc,
    const int* __restrict__ context_ids)
{
    const int warp = threadIdx.x >> 5;
    const int lane = threadIdx.x & 31;
    const int b = blockIdx.x * 4 + warp;

    // online combine of (max, sumexp) partials
    float m = -INFINITY, s = 0.f;
    for (int ch = lane; ch < NCHUNK; ch += 32) {
        float m2 = g_pmax[b * NCHUNK + ch];
        float s2 = g_psum[b * NCHUNK + ch];
        if (m2 > m) { s = s * __expf(m - m2) + s2; m = m2; }
        else        { s += s2 * __expf(m2 - m); }
    }
    #pragma unroll
    for (int o = 16; o; o >>= 1) {
        float m2 = __shfl_xor_sync(0xffffffffu, m, o);
        float s2 = __shfl_xor_sync(0xffffffffu, s, o);
        if (m2 > m) { s = s * __expf(m - m2) + s2; m = m2; }
        else        { s += s2 * __expf(m2 - m); }
    }
    float lse = m + logf(s);

    float zr[4];
    #pragma unroll
    for (int t = 0; t < 4; t++) zr[t] = g_z[b * D + lane + 32 * t];

    float rec = 0.f;
    #pragma unroll
    for (int c = 0; c < C; c++) {
        int v = context_ids[b * C + c];
        float p = 0.f;
        #pragma unroll
        for (int t = 0; t < 4; t++)
            p = fmaf(zr[t], Wv[(lane + 32 * t) * V + v], p);
        #pragma unroll
        for (int o = 16; o; o >>= 1) p += __shfl_xor_sync(0xffffffffu, p, o);
        rec += p + bvoc[v] - lse;   // identical on all lanes after full reduce
    }
    if (lane == 0) g_rowval[b] = rec - g_kl[b];
}

// ---------------- kernel 4: deterministic mean over B ----------------
__global__ void __launch_bounds__(1024) reduce_mean(float* __restrict__ out)
{
    __shared__ float red_s[32];
    const int tid = threadIdx.x;
    float v = g_rowval[tid];
    #pragma unroll
    for (int o = 16; o; o >>= 1) v += __shfl_xor_sync(0xffffffffu, v, o);
    if ((tid & 31) == 0) red_s[tid >> 5] = v;
    __syncthreads();
    if (tid < 32) {
        float sv = red_s[tid];
        #pragma unroll
        for (int o = 16; o; o >>= 1) sv += __shfl_xor_sync(0xffffffffu, sv, o);
        if (tid == 0) out[0] = sv * (1.0f / (float)B);
    }
}

// ---------------- launch ----------------
extern "C" void kernel_launch(void* const* d_in, const int* in_sizes, int n_in,
                              void* d_out, int out_size)
{
    const int*   center_id   = (const int*)d_in[0];
    const int*   context_ids = (const int*)d_in[1];
    const float* epsilon     = (const float*)d_in[2];
    const float* emb         = (const float*)d_in[3];
    const float* prior_means = (const float*)d_in[4];
    const float* prior_vars  = (const float*)d_in[5];
    const float* W_enc       = (const float*)d_in[6];
    const float* b_enc       = (const float*)d_in[7];
    const float* W_mean      = (const float*)d_in[8];
    const float* b_mean      = (const float*)d_in[9];
    const float* W_var       = (const float*)d_in[10];
    const float* b_var       = (const float*)d_in[11];
    const float* W_vocab     = (const float*)d_in[12];
    const float* b_vocab     = (const float*)d_in[13];
    float* out = (float*)d_out;

    encoder_kernel<<<B, 256>>>(center_id, context_ids, epsilon, emb,
                               prior_means, prior_vars,
                               W_enc, b_enc, W_mean, b_mean, W_var, b_var);

    dim3 grid2(NCHUNK, B / BT);
    vocab_kernel<<<grid2, 256>>>(W_vocab, b_vocab);

    finalize_rows<<<B / 4, 128>>>(W_vocab, b_vocab, context_ids);

    reduce_mean<<<1, 1024>>>(out);
}

// round 2
// speedup vs baseline: 2.7259x; 2.7259x over previous
#include <cuda_runtime.h>
#include <cuda_bf16.h>
#include <math.h>

#define V 50257
#define D 128
#define B 1024
#define C 10
#define TWO_D 256

// vocab GEMM tiling (tensor-core version)
#define M_CTA 128
#define N_CTA 128
#define KT 32
#define WS_STRIDE 136               // 128 + 8 pad -> conflict-free fragment loads
#define NCHUNK ((V + N_CTA - 1) / N_CTA)   // 393

// ---------------- scratch (no cudaMalloc allowed) ----------------
__device__ float g_z[B * D];
__device__ float g_kl[B];
__device__ float g_pmax[B * NCHUNK];
__device__ float g_psum[B * NCHUNK];
__device__ float g_rowval[B];

__device__ __forceinline__ float softplus_f(float x) {
    return fmaxf(x, 0.f) + log1pf(expf(-fabsf(x)));
}

__device__ __forceinline__ unsigned f2tf32(float x) {
    unsigned r;
    asm("cvt.rna.tf32.f32 %0, %1;" : "=r"(r) : "f"(x));
    return r;
}

__device__ __forceinline__ void mma_tf32(float c[4],
                                         unsigned a0, unsigned a1, unsigned a2, unsigned a3,
                                         unsigned b0, unsigned b1) {
    asm volatile(
        "mma.sync.aligned.m16n8k8.row.col.f32.tf32.tf32.f32 "
        "{%0,%1,%2,%3}, {%4,%5,%6,%7}, {%8,%9}, {%0,%1,%2,%3};"
        : "+f"(c[0]), "+f"(c[1]), "+f"(c[2]), "+f"(c[3])
        : "r"(a0), "r"(a1), "r"(a2), "r"(a3), "r"(b0), "r"(b1));
}

// ---------------- kernel 1: encoder + heads + KL + z ----------------
__global__ void __launch_bounds__(256) encoder_kernel(
    const int* __restrict__ center_id, const int* __restrict__ context_ids,
    const float* __restrict__ epsilon, const float* __restrict__ emb,
    const float* __restrict__ prior_means, const float* __restrict__ prior_vars,
    const float* __restrict__ W_enc, const float* __restrict__ b_enc,
    const float* __restrict__ W_mean, const float* __restrict__ b_mean,
    const float* __restrict__ W_var, const float* __restrict__ b_var)
{
    __shared__ float ce_s[D];
    __shared__ float cx_s[C][D];
    __shared__ float h_s[TWO_D];
    __shared__ float mean_s[D];
    __shared__ float var_s[D];
    __shared__ int   ctx_s[C];
    __shared__ float red_s[8];

    const int b = blockIdx.x;
    const int tid = threadIdx.x;
    const int cid = center_id[b];

    if (tid < D) ce_s[tid] = emb[cid * D + tid];
    if (tid < C) ctx_s[tid] = context_ids[b * C + tid];
    __syncthreads();
    for (int e = tid; e < C * D; e += 256) {
        int c = e >> 7, d = e & 127;
        cx_s[c][d] = emb[ctx_s[c] * D + d];
    }
    __syncthreads();

    const int j = tid;
    float cepart = 0.f;
    #pragma unroll 4
    for (int k = 0; k < D; k++)
        cepart = fmaf(ce_s[k], W_enc[k * TWO_D + j], cepart);

    float acc[C];
    #pragma unroll
    for (int c = 0; c < C; c++) acc[c] = 0.f;
    #pragma unroll 2
    for (int k = 0; k < D; k++) {
        float w = W_enc[(D + k) * TWO_D + j];
        #pragma unroll
        for (int c = 0; c < C; c++)
            acc[c] = fmaf(cx_s[c][k], w, acc[c]);
    }
    float base = cepart + b_enc[j];
    float hj = 0.f;
    #pragma unroll
    for (int c = 0; c < C; c++) hj += fmaxf(acc[c] + base, 0.f);
    h_s[j] = hj;
    __syncthreads();

    if (tid < D) {
        float m = b_mean[tid];
        #pragma unroll 4
        for (int k = 0; k < TWO_D; k++)
            m = fmaf(h_s[k], W_mean[k * D + tid], m);
        mean_s[tid] = m;
    } else {
        int d = tid - D;
        float vr = b_var[d];
        #pragma unroll 4
        for (int k = 0; k < TWO_D; k++)
            vr = fmaf(h_s[k], W_var[k * D + d], vr);
        var_s[d] = softplus_f(vr);
    }
    __syncthreads();

    float term = 0.f;
    if (tid < D) {
        int d = tid;
        float m = mean_s[d];
        float v = var_s[d];
        g_z[b * D + d] = m + expf(0.5f * v) * epsilon[d];
        float pm = prior_means[cid * D + d];
        float pv = softplus_f(prior_vars[cid * D + d]);
        float diff = pm - m;
        term = v / pv + diff * diff / pv - 1.f + logf(pv) - logf(v);
    }
    #pragma unroll
    for (int o = 16; o; o >>= 1) term += __shfl_xor_sync(0xffffffffu, term, o);
    if ((tid & 31) == 0) red_s[tid >> 5] = term;
    __syncthreads();
    if (tid == 0) {
        float s = 0.f;
        #pragma unroll
        for (int w = 0; w < 8; w++) s += red_s[w];
        g_kl[b] = 0.5f * s;
    }
}

// ---------------- kernel 2: tf32 tensor-core vocab GEMM + fused softmax partials ----
// CTA: 128 rows x 128 vocab cols. 8 warps; warp w owns rows [16w, 16w+16),
// covering all 128 cols as 16 m16n8 tiles. A (z) from global (L1-hot),
// B (W_vocab) tf32-converted in smem with stride-136 padding (conflict-free).
__global__ void __launch_bounds__(256) vocab_kernel(
    const float* __restrict__ Wv, const float* __restrict__ bvoc)
{
    __shared__ unsigned Ws[KT * WS_STRIDE];   // tf32 bits, 17408 B

    const int tid  = threadIdx.x;
    const int lane = tid & 31;
    const int w    = tid >> 5;
    const int g    = lane >> 2;   // group id: row within m16 half
    const int cg   = lane & 3;    // thread in group: k offset / col pair
    const int v0   = blockIdx.x * N_CTA;
    const int b0   = blockIdx.y * M_CTA;

    const float* zrow0 = g_z + (b0 + w * 16 + g) * D;
    const float* zrow1 = zrow0 + 8 * D;

    float acc[16][4];
    #pragma unroll
    for (int t = 0; t < 16; t++)
        #pragma unroll
        for (int i = 0; i < 4; i++) acc[t][i] = 0.f;

    for (int k0 = 0; k0 < D; k0 += KT) {
        // fill B tile: Ws[kk][n] = tf32(Wv[(k0+kk)*V + v0+n])
        #pragma unroll
        for (int e = tid; e < KT * N_CTA; e += 256) {
            int kk = e >> 7, n = e & 127;
            int v = v0 + n;
            float wv = (v < V) ? Wv[(k0 + kk) * V + v] : 0.f;
            Ws[kk * WS_STRIDE + n] = f2tf32(wv);
        }
        __syncthreads();

        #pragma unroll
        for (int ks = 0; ks < KT; ks += 8) {
            const int k = k0 + ks;
            unsigned a0 = f2tf32(zrow0[k + cg]);
            unsigned a1 = f2tf32(zrow1[k + cg]);
            unsigned a2 = f2tf32(zrow0[k + cg + 4]);
            unsigned a3 = f2tf32(zrow1[k + cg + 4]);
            const unsigned* wsb0 = Ws + (ks + cg) * WS_STRIDE + g;
            const unsigned* wsb1 = Ws + (ks + cg + 4) * WS_STRIDE + g;
            #pragma unroll
            for (int t = 0; t < 16; t++) {
                unsigned b0r = wsb0[t * 8];
                unsigned b1r = wsb1[t * 8];
                mma_tf32(acc[t], a0, a1, a2, a3, b0r, b1r);
            }
        }
        __syncthreads();
    }

    // epilogue: bias + mask + per-row max/sumexp over this 128-col chunk.
    // thread holds rows r0 = 16w+g (c0,c1) and r1 = r0+8 (c2,c3); cols t*8+2cg{,+1}
    const int chunk = blockIdx.x;
    float m0 = -INFINITY, m1 = -INFINITY;
    #pragma unroll
    for (int t = 0; t < 16; t++) {
        int n = t * 8 + 2 * cg;
        bool ok0 = (v0 + n) < V;
        bool ok1 = (v0 + n + 1) < V;
        float bv0 = ok0 ? bvoc[v0 + n] : 0.f;
        float bv1 = ok1 ? bvoc[v0 + n + 1] : 0.f;
        acc[t][0] = ok0 ? acc[t][0] + bv0 : -INFINITY;
        acc[t][1] = ok1 ? acc[t][1] + bv1 : -INFINITY;
        acc[t][2] = ok0 ? acc[t][2] + bv0 : -INFINITY;
        acc[t][3] = ok1 ? acc[t][3] + bv1 : -INFINITY;
        m0 = fmaxf(m0, fmaxf(acc[t][0], acc[t][1]));
        m1 = fmaxf(m1, fmaxf(acc[t][2], acc[t][3]));
    }
    // reduce over the 4-thread group (lanes sharing lane>>2)
    #pragma unroll
    for (int o = 1; o <= 2; o <<= 1) {
        m0 = fmaxf(m0, __shfl_xor_sync(0xffffffffu, m0, o));
        m1 = fmaxf(m1, __shfl_xor_sync(0xffffffffu, m1, o));
    }
    float s0 = 0.f, s1 = 0.f;
    #pragma unroll
    for (int t = 0; t < 16; t++) {
        s0 += __expf(acc[t][0] - m0) + __expf(acc[t][1] - m0);
        s1 += __expf(acc[t][2] - m1) + __expf(acc[t][3] - m1);
    }
    #pragma unroll
    for (int o = 1; o <= 2; o <<= 1) {
        s0 += __shfl_xor_sync(0xffffffffu, s0, o);
        s1 += __shfl_xor_sync(0xffffffffu, s1, o);
    }
    if (cg == 0) {
        int r0 = b0 + w * 16 + g;
        g_pmax[r0 * NCHUNK + chunk] = m0;
        g_psum[r0 * NCHUNK + chunk] = s0;
        g_pmax[(r0 + 8) * NCHUNK + chunk] = m1;
        g_psum[(r0 + 8) * NCHUNK + chunk] = s1;
    }
}

// ---------------- kernel 3: per-row logsumexp combine + context gather ----------------
__global__ void __launch_bounds__(128) finalize_rows(
    const float* __restrict__ Wv, const float* __restrict__ bvoc,
    const int* __restrict__ context_ids)
{
    const int warp = threadIdx.x >> 5;
    const int lane = threadIdx.x & 31;
    const int b = blockIdx.x * 4 + warp;

    float m = -INFINITY, s = 0.f;
    for (int ch = lane; ch < NCHUNK; ch += 32) {
        float m2 = g_pmax[b * NCHUNK + ch];
        float s2 = g_psum[b * NCHUNK + ch];
        if (m2 > m) { s = s * __expf(m - m2) + s2; m = m2; }
        else        { s += s2 * __expf(m2 - m); }
    }
    #pragma unroll
    for (int o = 16; o; o >>= 1) {
        float m2 = __shfl_xor_sync(0xffffffffu, m, o);
        float s2 = __shfl_xor_sync(0xffffffffu, s, o);
        if (m2 > m) { s = s * __expf(m - m2) + s2; m = m2; }
        else        { s += s2 * __expf(m2 - m); }
    }
    float lse = m + logf(s);

    float zr[4];
    #pragma unroll
    for (int t = 0; t < 4; t++) zr[t] = g_z[b * D + lane + 32 * t];

    float rec = 0.f;
    #pragma unroll
    for (int c = 0; c < C; c++) {
        int v = context_ids[b * C + c];
        float p = 0.f;
        #pragma unroll
        for (int t = 0; t < 4; t++)
            p = fmaf(zr[t], Wv[(lane + 32 * t) * V + v], p);
        #pragma unroll
        for (int o = 16; o; o >>= 1) p += __shfl_xor_sync(0xffffffffu, p, o);
        rec += p + bvoc[v] - lse;
    }
    if (lane == 0) g_rowval[b] = rec - g_kl[b];
}

// ---------------- kernel 4: deterministic mean over B ----------------
__global__ void __launch_bounds__(1024) reduce_mean(float* __restrict__ out)
{
    __shared__ float red_s[32];
    const int tid = threadIdx.x;
    float v = g_rowval[tid];
    #pragma unroll
    for (int o = 16; o; o >>= 1) v += __shfl_xor_sync(0xffffffffu, v, o);
    if ((tid & 31) == 0) red_s[tid >> 5] = v;
    __syncthreads();
    if (tid < 32) {
        float sv = red_s[tid];
        #pragma unroll
        for (int o = 16; o; o >>= 1) sv += __shfl_xor_sync(0xffffffffu, sv, o);
        if (tid == 0) out[0] = sv * (1.0f / (float)B);
    }
}

// ---------------- launch ----------------
extern "C" void kernel_launch(void* const* d_in, const int* in_sizes, int n_in,
                              void* d_out, int out_size)
{
    const int*   center_id   = (const int*)d_in[0];
    const int*   context_ids = (const int*)d_in[1];
    const float* epsilon     = (const float*)d_in[2];
    const float* emb         = (const float*)d_in[3];
    const float* prior_means = (const float*)d_in[4];
    const float* prior_vars  = (const float*)d_in[5];
    const float* W_enc       = (const float*)d_in[6];
    const float* b_enc       = (const float*)d_in[7];
    const float* W_mean      = (const float*)d_in[8];
    const float* b_mean      = (const float*)d_in[9];
    const float* W_var       = (const float*)d_in[10];
    const float* b_var       = (const float*)d_in[11];
    const float* W_vocab     = (const float*)d_in[12];
    const float* b_vocab     = (const float*)d_in[13];
    float* out = (float*)d_out;

    encoder_kernel<<<B, 256>>>(center_id, context_ids, epsilon, emb,
                               prior_means, prior_vars,
                               W_enc, b_enc, W_mean, b_mean, W_var, b_var);

    dim3 grid2(NCHUNK, B / M_CTA);
    vocab_kernel<<<grid2, 256>>>(W_vocab, b_vocab);

    finalize_rows<<<B / 4, 128>>>(W_vocab, b_vocab, context_ids);

    reduce_mean<<<1, 1024>>>(out);
}

// round 5
// speedup vs baseline: 2.7494x; 1.0086x over previous
#include <cuda_runtime.h>
#include <cuda_fp16.h>
#include <cuda_bf16.h>
#include <math.h>
#include <stdint.h>

#define V 50257
#define D 128
#define B 1024
#define C 10
#define TWO_D 256
#define NB 4                 // batch rows per encoder CTA

// vocab GEMM tiling (fp16 mma.sync m16n8k16)
#define M_CTA 128
#define N_CTA 128
#define KT 32                              // k per smem stage (16 half2 rows)
#define WS_STRIDE 136                      // half2 units; 136 mod 32 = 8 -> conflict-free
#define WS_BUF (16 * WS_STRIDE)            // 2176 words per stage
#define NCHUNK ((V + N_CTA - 1) / N_CTA)   // 393

// ---------------- scratch ----------------
__device__ float    g_z[B * D];
__device__ unsigned g_zh2[B * D / 2];      // packed half2 z
__device__ float    g_kl[B];
__device__ float    g_pmax[B * NCHUNK];
__device__ float    g_psum[B * NCHUNK];
__device__ float    g_rowval[B];

__device__ __forceinline__ float softplus_f(float x) {
    return fmaxf(x, 0.f) + log1pf(expf(-fabsf(x)));
}

__device__ __forceinline__ void mma_f16(float c[4],
                                        unsigned a0, unsigned a1, unsigned a2, unsigned a3,
                                        unsigned b0, unsigned b1) {
    asm volatile(
        "mma.sync.aligned.m16n8k16.row.col.f32.f16.f16.f32 "
        "{%0,%1,%2,%3}, {%4,%5,%6,%7}, {%8,%9}, {%0,%1,%2,%3};"
        : "+f"(c[0]), "+f"(c[1]), "+f"(c[2]), "+f"(c[3])
        : "r"(a0), "r"(a1), "r"(a2), "r"(a3), "r"(b0), "r"(b1));
}

// ---------------- kernel 1: encoder (NB=4 rows/CTA) + heads + KL + z ----------------
__global__ void __launch_bounds__(256) encoder_kernel(
    const int* __restrict__ center_id, const int* __restrict__ context_ids,
    const float* __restrict__ epsilon, const float* __restrict__ emb,
    const float* __restrict__ prior_means, const float* __restrict__ prior_vars,
    const float* __restrict__ W_enc, const float* __restrict__ b_enc,
    const float* __restrict__ W_mean, const float* __restrict__ b_mean,
    const float* __restrict__ W_var, const float* __restrict__ b_var)
{
    __shared__ float ce_s[NB][D];
    __shared__ float cx_s[NB][C][D];
    __shared__ float h_s[NB][TWO_D];
    __shared__ float mean_s[NB][D];
    __shared__ float var_s[NB][D];
    __shared__ int   ctx_s[NB][C];
    __shared__ int   cid_s[NB];
    __shared__ float red_s[NB][4];

    const int b0  = blockIdx.x * NB;
    const int tid = threadIdx.x;

    if (tid < NB) cid_s[tid] = center_id[b0 + tid];
    if (tid < NB * C) ctx_s[tid / C][tid % C] = context_ids[b0 * C + tid];
    __syncthreads();
    for (int e = tid; e < NB * D; e += 256) {
        int nb = e >> 7, d = e & 127;
        ce_s[nb][d] = emb[cid_s[nb] * D + d];
    }
    for (int e = tid; e < NB * C * D; e += 256) {
        int nb = e / (C * D), r = e % (C * D);
        int c = r >> 7, d = r & 127;
        cx_s[nb][c][d] = emb[ctx_s[nb][c] * D + d];
    }
    __syncthreads();

    const int j = tid;
    float cepart[NB];
    #pragma unroll
    for (int nb = 0; nb < NB; nb++) cepart[nb] = 0.f;
    #pragma unroll 2
    for (int k = 0; k < D; k++) {
        float w1 = W_enc[k * TWO_D + j];
        #pragma unroll
        for (int nb = 0; nb < NB; nb++)
            cepart[nb] = fmaf(ce_s[nb][k], w1, cepart[nb]);
    }

    float acc[NB][C];
    #pragma unroll
    for (int nb = 0; nb < NB; nb++)
        #pragma unroll
        for (int c = 0; c < C; c++) acc[nb][c] = 0.f;
    for (int k = 0; k < D; k++) {
        float w2 = W_enc[(D + k) * TWO_D + j];
        #pragma unroll
        for (int nb = 0; nb < NB; nb++)
            #pragma unroll
            for (int c = 0; c < C; c++)
                acc[nb][c] = fmaf(cx_s[nb][c][k], w2, acc[nb][c]);
    }
    float be = b_enc[j];
    #pragma unroll
    for (int nb = 0; nb < NB; nb++) {
        float base = cepart[nb] + be;
        float hj = 0.f;
        #pragma unroll
        for (int c = 0; c < C; c++) hj += fmaxf(acc[nb][c] + base, 0.f);
        h_s[nb][j] = hj;
    }
    __syncthreads();

    if (tid < D) {
        int d = tid;
        float m[NB];
        #pragma unroll
        for (int nb = 0; nb < NB; nb++) m[nb] = b_mean[d];
        #pragma unroll 2
        for (int k = 0; k < TWO_D; k++) {
            float wm = W_mean[k * D + d];
            #pragma unroll
            for (int nb = 0; nb < NB; nb++)
                m[nb] = fmaf(h_s[nb][k], wm, m[nb]);
        }
        #pragma unroll
        for (int nb = 0; nb < NB; nb++) mean_s[nb][d] = m[nb];
    } else {
        int d = tid - D;
        float vr[NB];
        #pragma unroll
        for (int nb = 0; nb < NB; nb++) vr[nb] = b_var[d];
        #pragma unroll 2
        for (int k = 0; k < TWO_D; k++) {
            float wv = W_var[k * D + d];
            #pragma unroll
            for (int nb = 0; nb < NB; nb++)
                vr[nb] = fmaf(h_s[nb][k], wv, vr[nb]);
        }
        #pragma unroll
        for (int nb = 0; nb < NB; nb++) var_s[nb][d] = softplus_f(vr[nb]);
    }
    __syncthreads();

    float term[NB];
    #pragma unroll
    for (int nb = 0; nb < NB; nb++) term[nb] = 0.f;
    if (tid < D) {
        int d = tid;
        float eps = epsilon[d];
        #pragma unroll
        for (int nb = 0; nb < NB; nb++) {
            int b = b0 + nb;
            float m = mean_s[nb][d];
            float v = var_s[nb][d];
            float z = m + expf(0.5f * v) * eps;
            g_z[b * D + d] = z;
            float zn = __shfl_down_sync(0xffffffffu, z, 1);
            if (!(d & 1)) {
                __half2 hz = __floats2half2_rn(z, zn);
                g_zh2[(b * D + d) >> 1] = *(unsigned*)&hz;
            }
            float pm = prior_means[cid_s[nb] * D + d];
            float pv = softplus_f(prior_vars[cid_s[nb] * D + d]);
            float diff = pm - m;
            term[nb] = v / pv + diff * diff / pv - 1.f + logf(pv) - logf(v);
        }
    }
    #pragma unroll
    for (int nb = 0; nb < NB; nb++) {
        float t = term[nb];
        #pragma unroll
        for (int o = 16; o; o >>= 1) t += __shfl_xor_sync(0xffffffffu, t, o);
        if (tid < D && (tid & 31) == 0) red_s[nb][tid >> 5] = t;
    }
    __syncthreads();
    if (tid < NB) {
        float s = red_s[tid][0] + red_s[tid][1] + red_s[tid][2] + red_s[tid][3];
        g_kl[b0 + tid] = 0.5f * s;
    }
}

// ---------------- kernel 2: fp16 mma.sync vocab GEMM + fused softmax partials ----
// CTA: 128 rows x 128 vocab cols; 8 warps; warp w owns rows [16w,16w+16).
// A (z half2) from global; B (W_vocab) half2-packed in smem, double-buffered,
// register-prefetched. Stride 136 -> conflict-free fragment loads.
__global__ void __launch_bounds__(256) vocab_kernel(
    const float* __restrict__ Wv, const float* __restrict__ bvoc)
{
    __shared__ unsigned Ws[2 * WS_BUF];     // 17408 B

    const int tid  = threadIdx.x;
    const int lane = tid & 31;
    const int w    = tid >> 5;
    const int g    = lane >> 2;
    const int cg   = lane & 3;
    const int v0   = blockIdx.x * N_CTA;
    const int b0   = blockIdx.y * M_CTA;

    const unsigned* zh0 = g_zh2 + (b0 + w * 16 + g) * (D / 2);
    const unsigned* zh1 = zh0 + 8 * (D / 2);

    // fill indexing: n fixed per thread, k2 = (tid>>7) + 2i
    const int n_f  = tid & 127;
    const int k2b  = tid >> 7;
    const int vf   = v0 + n_f;
    const bool okf = (vf < V);
    const float* wp = Wv + (okf ? vf : 0);

    float acc[16][4];
    #pragma unroll
    for (int t = 0; t < 16; t++)
        #pragma unroll
        for (int i = 0; i < 4; i++) acc[t][i] = 0.f;

    float plo[8], phi[8];
    #define LOADREGS(K0) do {                                                 \
        _Pragma("unroll")                                                     \
        for (int i = 0; i < 8; i++) {                                         \
            int kk = (K0) + 2 * (k2b + 2 * i);                                \
            plo[i] = okf ? wp[kk * V] : 0.f;                                  \
            phi[i] = okf ? wp[(kk + 1) * V] : 0.f;                            \
        } } while (0)
    #define STOREREGS(BUF) do {                                               \
        _Pragma("unroll")                                                     \
        for (int i = 0; i < 8; i++) {                                         \
            __half2 hv = __floats2half2_rn(plo[i], phi[i]);                   \
            (BUF)[(k2b + 2 * i) * WS_STRIDE + n_f] = *(unsigned*)&hv;         \
        } } while (0)

    LOADREGS(0);
    #pragma unroll
    for (int it = 0; it < 4; it++) {
        unsigned* buf = Ws + (it & 1) * WS_BUF;
        STOREREGS(buf);
        __syncthreads();
        if (it < 3) LOADREGS((it + 1) * KT);

        const int k0 = it * KT;
        #pragma unroll
        for (int ks = 0; ks < KT; ks += 16) {
            const int kh = (k0 + ks) >> 1;       // half2 index into z row
            unsigned a0 = zh0[kh + cg];
            unsigned a1 = zh1[kh + cg];
            unsigned a2 = zh0[kh + cg + 4];
            unsigned a3 = zh1[kh + cg + 4];
            const unsigned* wsb0 = buf + ((ks >> 1) + cg) * WS_STRIDE + g;
            const unsigned* wsb1 = wsb0 + 4 * WS_STRIDE;
            #pragma unroll
            for (int t = 0; t < 16; t++)
                mma_f16(acc[t], a0, a1, a2, a3, wsb0[t * 8], wsb1[t * 8]);
        }
    }
    #undef LOADREGS
    #undef STOREREGS

    // epilogue: bias + mask + per-row max/sumexp over this 128-col chunk.
    // thread holds rows r0=16w+g (c0,c1) and r1=r0+8 (c2,c3); cols t*8+2cg{,+1}
    const int chunk = blockIdx.x;
    float m0 = -INFINITY, m1 = -INFINITY;
    #pragma unroll
    for (int t = 0; t < 16; t++) {
        int n = t * 8 + 2 * cg;
        bool ok0 = (v0 + n) < V;
        bool ok1 = (v0 + n + 1) < V;
        float bv0 = ok0 ? bvoc[v0 + n] : 0.f;
        float bv1 = ok1 ? bvoc[v0 + n + 1] : 0.f;
        acc[t][0] = ok0 ? acc[t][0] + bv0 : -INFINITY;
        acc[t][1] = ok1 ? acc[t][1] + bv1 : -INFINITY;
        acc[t][2] = ok0 ? acc[t][2] + bv0 : -INFINITY;
        acc[t][3] = ok1 ? acc[t][3] + bv1 : -INFINITY;
        m0 = fmaxf(m0, fmaxf(acc[t][0], acc[t][1]));
        m1 = fmaxf(m1, fmaxf(acc[t][2], acc[t][3]));
    }
    #pragma unroll
    for (int o = 1; o <= 2; o <<= 1) {
        m0 = fmaxf(m0, __shfl_xor_sync(0xffffffffu, m0, o));
        m1 = fmaxf(m1, __shfl_xor_sync(0xffffffffu, m1, o));
    }
    float s0 = 0.f, s1 = 0.f;
    #pragma unroll
    for (int t = 0; t < 16; t++) {
        s0 += __expf(acc[t][0] - m0) + __expf(acc[t][1] - m0);
        s1 += __expf(acc[t][2] - m1) + __expf(acc[t][3] - m1);
    }
    #pragma unroll
    for (int o = 1; o <= 2; o <<= 1) {
        s0 += __shfl_xor_sync(0xffffffffu, s0, o);
        s1 += __shfl_xor_sync(0xffffffffu, s1, o);
    }
    if (cg == 0) {
        int r0 = b0 + w * 16 + g;
        g_pmax[r0 * NCHUNK + chunk] = m0;
        g_psum[r0 * NCHUNK + chunk] = s0;
        g_pmax[(r0 + 8) * NCHUNK + chunk] = m1;
        g_psum[(r0 + 8) * NCHUNK + chunk] = s1;
    }
}

// ---------------- kernel 3: per-row logsumexp combine + context gather ----------------
__global__ void __launch_bounds__(128) finalize_rows(
    const float* __restrict__ Wv, const float* __restrict__ bvoc,
    const int* __restrict__ context_ids)
{
    const int warp = threadIdx.x >> 5;
    const int lane = threadIdx.x & 31;
    const int b = blockIdx.x * 4 + warp;

    float m = -INFINITY, s = 0.f;
    for (int ch = lane; ch < NCHUNK; ch += 32) {
        float m2 = g_pmax[b * NCHUNK + ch];
        float s2 = g_psum[b * NCHUNK + ch];
        if (m2 > m) { s = s * __expf(m - m2) + s2; m = m2; }
        else        { s += s2 * __expf(m2 - m); }
    }
    #pragma unroll
    for (int o = 16; o; o >>= 1) {
        float m2 = __shfl_xor_sync(0xffffffffu, m, o);
        float s2 = __shfl_xor_sync(0xffffffffu, s, o);
        if (m2 > m) { s = s * __expf(m - m2) + s2; m = m2; }
        else        { s += s2 * __expf(m2 - m); }
    }
    float lse = m + logf(s);

    float zr[4];
    #pragma unroll
    for (int t = 0; t < 4; t++) zr[t] = g_z[b * D + lane + 32 * t];

    float rec = 0.f;
    #pragma unroll
    for (int c = 0; c < C; c++) {
        int v = context_ids[b * C + c];
        float p = 0.f;
        #pragma unroll
        for (int t = 0; t < 4; t++)
            p = fmaf(zr[t], Wv[(lane + 32 * t) * V + v], p);
        #pragma unroll
        for (int o = 16; o; o >>= 1) p += __shfl_xor_sync(0xffffffffu, p, o);
        rec += p + bvoc[v] - lse;
    }
    if (lane == 0) g_rowval[b] = rec - g_kl[b];
}

// ---------------- kernel 4: deterministic mean over B ----------------
__global__ void __launch_bounds__(1024) reduce_mean(float* __restrict__ out)
{
    __shared__ float red_s[32];
    const int tid = threadIdx.x;
    float v = g_rowval[tid];
    #pragma unroll
    for (int o = 16; o; o >>= 1) v += __shfl_xor_sync(0xffffffffu, v, o);
    if ((tid & 31) == 0) red_s[tid >> 5] = v;
    __syncthreads();
    if (tid < 32) {
        float sv = red_s[tid];
        #pragma unroll
        for (int o = 16; o; o >>= 1) sv += __shfl_xor_sync(0xffffffffu, sv, o);
        if (tid == 0) out[0] = sv * (1.0f / (float)B);
    }
}

// ---------------- launch ----------------
extern "C" void kernel_launch(void* const* d_in, const int* in_sizes, int n_in,
                              void* d_out, int out_size)
{
    const int*   center_id   = (const int*)d_in[0];
    const int*   context_ids = (const int*)d_in[1];
    const float* epsilon     = (const float*)d_in[2];
    const float* emb         = (const float*)d_in[3];
    const float* prior_means = (const float*)d_in[4];
    const float* prior_vars  = (const float*)d_in[5];
    const float* W_enc       = (const float*)d_in[6];
    const float* b_enc       = (const float*)d_in[7];
    const float* W_mean      = (const float*)d_in[8];
    const float* b_mean      = (const float*)d_in[9];
    const float* W_var       = (const float*)d_in[10];
    const float* b_var       = (const float*)d_in[11];
    const float* W_vocab     = (const float*)d_in[12];
    const float* b_vocab     = (const float*)d_in[13];
    float* out = (float*)d_out;

    encoder_kernel<<<B / NB, 256>>>(center_id, context_ids, epsilon, emb,
                                    prior_means, prior_vars,
                                    W_enc, b_enc, W_mean, b_mean, W_var, b_var);

    dim3 grid2(NCHUNK, B / M_CTA);
    vocab_kernel<<<grid2, 256>>>(W_vocab, b_vocab);

    finalize_rows<<<B / 4, 128>>>(W_vocab, b_vocab, context_ids);

    reduce_mean<<<1, 1024>>>(out);
}